// round 7
// baseline (speedup 1.0000x reference)
#include <cuda_runtime.h>
#include <cstdint>

#define N_ETA 7
#define FDIM 68
#define HW (512*1024)
#define CHUNK 1772               // mult of 4; 296 chunks
#define NCHUNKS ((HW + CHUNK - 1) / CHUNK)   // 296
#define STRIDE 1776              // feat tile row stride (floats)
#define WSZ (N_ETA*FDIM*FDIM)    // 32368

__device__ unsigned char g_eta[HW];

// ---------------- threefry2x32, key (0,42), jax partitionable path ----------------
__device__ __forceinline__ void threefry2x32_k42(uint32_t& x0, uint32_t& x1) {
    const uint32_t K2 = 0x1BD11BDAu ^ 0u ^ 42u;
#define TFR(r) { x0 += x1; x1 = __funnelshift_l(x1, x1, (r)); x1 ^= x0; }
    x1 += 42u;
    TFR(13) TFR(15) TFR(26) TFR(6)
    x0 += 42u;  x1 += K2 + 1u;
    TFR(17) TFR(29) TFR(16) TFR(24)
    x0 += K2;   x1 += 0u + 2u;
    TFR(13) TFR(15) TFR(26) TFR(6)
    x1 += 42u + 3u;
    TFR(17) TFR(29) TFR(16) TFR(24)
    x0 += 42u;  x1 += K2 + 4u;
    TFR(13) TFR(15) TFR(26) TFR(6)
    x0 += K2;   x1 += 0u + 5u;
#undef TFR
}

__device__ __forceinline__ float gumbel_from_bits(uint32_t bits) {
    float f = __uint_as_float((bits >> 9) | 0x3F800000u) - 1.0f;
    const float tiny = 1.1754943508222875e-38f;
    float u = fmaxf(tiny, f + tiny);
    return -logf(-logf(u));
}

__global__ void eta_kernel(const float* __restrict__ T, const int* __restrict__ eta) {
    __shared__ float logT[N_ETA * N_ETA];
    if (threadIdx.x < N_ETA * N_ETA)
        logT[threadIdx.x] = logf(T[threadIdx.x] + 1e-9f);
    __syncthreads();
    int p = blockIdx.x * blockDim.x + threadIdx.x;
    if (p >= HW) return;
    int r = eta[p] * N_ETA;
    float best = -3.0e38f;
    int a = 0;
#pragma unroll
    for (int k = 0; k < N_ETA; k++) {
        uint32_t x0 = 0u;
        uint32_t x1 = (uint32_t)(p * 7 + k);
        threefry2x32_k42(x0, x1);
        uint32_t bits = x0 ^ x1;
        float v = logT[r + k] + gumbel_from_bits(bits);
        if (v > best) { best = v; a = k; }
    }
    g_eta[p] = (unsigned char)a;
}

// ---------------- packed f32x2 + smem/async helpers ----------------
__device__ __forceinline__ unsigned long long pack_ff(float x, float y) {
    unsigned long long r;
    asm("mov.b64 %0, {%1, %2};" : "=l"(r) : "f"(x), "f"(y));
    return r;
}
__device__ __forceinline__ void unpack_ff(float& x, float& y, unsigned long long v) {
    asm("mov.b64 {%0, %1}, %2;" : "=f"(x), "=f"(y) : "l"(v));
}
__device__ __forceinline__ void fma2(unsigned long long& acc, unsigned long long w, unsigned long long v) {
    asm("fma.rn.f32x2 %0, %1, %2, %0;" : "+l"(acc) : "l"(w), "l"(v));
}
__device__ __forceinline__ void lds_v2u64(unsigned long long& a, unsigned long long& b, const float* p) {
    asm("ld.shared.v2.u64 {%0, %1}, [%2];"
        : "=l"(a), "=l"(b) : "l"(__cvta_generic_to_shared(p)));
}
__device__ __forceinline__ unsigned long long lds_u64(const float* p) {
    unsigned long long r;
    asm("ld.shared.u64 %0, [%1];" : "=l"(r) : "l"(__cvta_generic_to_shared(p)));
    return r;
}
__device__ __forceinline__ void cp_async16(float* dst_smem, const float* src_gmem) {
    asm volatile("cp.async.ca.shared.global [%0], [%1], 16;"
                 :: "r"((uint32_t)__cvta_generic_to_shared(dst_smem)), "l"(src_gmem));
}
#define CP_COMMIT()  asm volatile("cp.async.commit_group;" ::: "memory")
#define CP_WAIT(n)   asm volatile("cp.async.wait_group %0;" :: "n"(n) : "memory")

// out[o,p] = sum_f W[e_p][o][f]*feat[f,p] + b[e_p][o]
// Per chunk: sort pixels into 32-px same-expert groups; warp = 1 group, lane = 1 px;
// W via full-warp BROADCAST LDS.128 (1 wf); feat via natural-order cp.async tiles.
__global__ __launch_bounds__(512, 1)
void compute_kernel(const float* __restrict__ feat, const float* __restrict__ W,
                    const float* __restrict__ b, float* __restrict__ out) {
    extern __shared__ float sh[];
    float* Wt   = sh;                         // [7][68 f][68 o] transposed
    float* bs   = Wt + WSZ;                   // 480 (uses 476)
    float* buf  = bs + 480;                   // 2 * 4 * STRIDE
    int*   s2o  = (int*)(buf + 2 * 4 * STRIDE);   // 2048
    int*   meta = s2o + 2048;                 // [0..6]=cnt [7]=ngroups [8..14]=cur

    const int tid = threadIdx.x;
    const int lane = tid & 31, warp = tid >> 5;

    // one-time: transpose W into smem, stage bias
    for (int i = tid; i < WSZ; i += 512) {
        int e = i / (FDIM * FDIM);
        int rem = i - e * (FDIM * FDIM);
        int f = rem / FDIM;
        int o = rem - f * FDIM;
        Wt[i] = W[(e * FDIM + o) * FDIM + f];
    }
    for (int i = tid; i < N_ETA * FDIM; i += 512) bs[i] = b[i];

    for (int c = blockIdx.x; c < NCHUNKS; c += gridDim.x) {
        const int cb = c * CHUNK;
        const int n = min(CHUNK, HW - cb);    // mult of 4

        // ---- sort chunk by expert into padded 32-px groups ----
        __syncthreads();                      // also covers Wt staging on first iter
        if (tid < 16) meta[tid] = 0;
        __syncthreads();
        for (int j = tid; j < n; j += 512) atomicAdd(&meta[g_eta[cb + j]], 1);
        __syncthreads();
        if (tid == 0) {
            int s = 0;
            for (int e = 0; e < N_ETA; e++) { meta[8 + e] = s; s += (meta[e] + 31) & ~31; }
            meta[7] = s >> 5;
        }
        __syncthreads();
        const int ngroups = meta[7];
        for (int s = tid; s < (ngroups << 5); s += 512) s2o[s] = -1;
        __syncthreads();
        for (int j = tid; j < n; j += 512) {
            int e = g_eta[cb + j];
            s2o[atomicAdd(&meta[8 + e], 1)] = j;
        }
        __syncthreads();

        const int nrounds = (ngroups + 15) >> 4;
        const int fl = tid >> 7, l128 = tid & 127;   // staging role
        const int n4 = n >> 2;

        for (int r = 0; r < nrounds; r++) {
            const int g = r * 16 + warp;
            const bool active = (g < ngroups);
            int orig = 0, e = 0;
            bool valid = false;
            if (active) {
                int o0 = s2o[g << 5];
                orig = s2o[(g << 5) + lane];
                valid = (orig >= 0);
                if (!valid) orig = o0;
                e = g_eta[cb + orig];
            }
            const float* wp = Wt + e * (FDIM * FDIM);
            const float* bp = bs + e * FDIM;

            unsigned long long acc[34];
            if (active) {
#pragma unroll
                for (int q = 0; q < 34; q++) acc[q] = lds_u64(bp + 2 * q);
            }

            // prologue: stage tile 0 into buf[0]
            {
                const float* src = feat + (size_t)fl * HW + cb;
                float* drow = buf + fl * STRIDE;
                for (int q = l128; q < n4; q += 128) cp_async16(drow + 4 * q, src + 4 * q);
                CP_COMMIT();
            }

            for (int t = 0; t < 17; t++) {
                if (t + 1 < 17) {
                    const float* src = feat + (size_t)(4 * (t + 1) + fl) * HW + cb;
                    float* drow = buf + ((t + 1) & 1) * 4 * STRIDE + fl * STRIDE;
                    for (int q = l128; q < n4; q += 128) cp_async16(drow + 4 * q, src + 4 * q);
                    CP_COMMIT();
                    CP_WAIT(1);
                } else {
                    CP_WAIT(0);
                }
                __syncthreads();
                if (active) {
                    const float* B = buf + (t & 1) * 4 * STRIDE + orig;
#pragma unroll
                    for (int ff = 0; ff < 4; ff++) {
                        float v = B[ff * STRIDE];
                        unsigned long long vv = pack_ff(v, v);
                        const float* wrow = wp + (4 * t + ff) * FDIM;
#pragma unroll
                        for (int q = 0; q < 17; q++) {
                            unsigned long long lo, hi;
                            lds_v2u64(lo, hi, wrow + 4 * q);   // broadcast: 1 wavefront
                            fma2(acc[2 * q], lo, vv);
                            fma2(acc[2 * q + 1], hi, vv);
                        }
                    }
                }
                __syncthreads();
            }

            // epilogue
            if (active && valid) {
                float* op = out + cb + orig;
#pragma unroll
                for (int q = 0; q < 34; q++) {
                    float x, y;
                    unpack_ff(x, y, acc[q]);
                    op[(size_t)(2 * q) * HW] = x;
                    op[(size_t)(2 * q + 1) * HW] = y;
                }
            }
        }
    }
}

extern "C" void kernel_launch(void* const* d_in, const int* in_sizes, int n_in,
                              void* d_out, int out_size) {
    const float* x   = 0;   // 35,651,584
    const float* W   = 0;   // 32,368
    const float* b   = 0;   // 476
    const float* T   = 0;   // 49
    const int*   eta = 0;   // 524,288
    for (int i = 0; i < n_in; i++) {
        switch (in_sizes[i]) {
            case 35651584: x   = (const float*)d_in[i]; break;
            case 32368:    W   = (const float*)d_in[i]; break;
            case 476:      b   = (const float*)d_in[i]; break;
            case 49:       T   = (const float*)d_in[i]; break;
            case 524288:   eta = (const int*)d_in[i];   break;
        }
    }
    float* out = (float*)d_out;

    eta_kernel<<<HW / 256, 256>>>(T, eta);

    int smem = (WSZ + 480 + 2 * 4 * STRIDE) * (int)sizeof(float)
             + (2048 + 16) * (int)sizeof(int);           // 196,480 B
    cudaFuncSetAttribute(compute_kernel, cudaFuncAttributeMaxDynamicSharedMemorySize, smem);
    int dev = 0, sms = 148;
    cudaGetDevice(&dev);
    cudaDeviceGetAttribute(&sms, cudaDevAttrMultiProcessorCount, dev);
    compute_kernel<<<sms, 512, smem>>>(x, W, b, out);
}

// round 8
// speedup vs baseline: 1.3483x; 1.3483x over previous
#include <cuda_runtime.h>
#include <cstdint>

#define N_ETA 7
#define FDIM 68
#define HW (512*1024)
#define CHUNK 480
#define NCH ((HW + CHUNK - 1) / CHUNK)    // 1093
#define MAXSL 21                           // 15 full + 6 pad groups
#define SLOTS (MAXSL*32)                   // 672
#define WSZ (N_ETA*FDIM*FDIM)              // 32368
#define TROWS 8                            // f-tile rows
#define TBUF (TROWS*CHUNK)                 // 3840 floats per buffer

__device__ uint16_t g_sorted[NCH * SLOTS];
__device__ int g_nsl[NCH];

// ---------------- threefry2x32, key (0,42), jax partitionable path ----------------
__device__ __forceinline__ void threefry2x32_k42(uint32_t& x0, uint32_t& x1) {
    const uint32_t K2 = 0x1BD11BDAu ^ 0u ^ 42u;
#define TFR(r) { x0 += x1; x1 = __funnelshift_l(x1, x1, (r)); x1 ^= x0; }
    x1 += 42u;
    TFR(13) TFR(15) TFR(26) TFR(6)
    x0 += 42u;  x1 += K2 + 1u;
    TFR(17) TFR(29) TFR(16) TFR(24)
    x0 += K2;   x1 += 0u + 2u;
    TFR(13) TFR(15) TFR(26) TFR(6)
    x1 += 42u + 3u;
    TFR(17) TFR(29) TFR(16) TFR(24)
    x0 += 42u;  x1 += K2 + 4u;
    TFR(13) TFR(15) TFR(26) TFR(6)
    x0 += K2;   x1 += 0u + 5u;
#undef TFR
}

__device__ __forceinline__ float gumbel_from_bits(uint32_t bits) {
    float f = __uint_as_float((bits >> 9) | 0x3F800000u) - 1.0f;
    const float tiny = 1.1754943508222875e-38f;
    float u = fmaxf(tiny, f + tiny);
    return -logf(-logf(u));
}

// eta + chunk-local expert sort with 32-px padded groups.
// entry: bits[0:9)=local px, [9:12)=expert, [12]=valid
__global__ __launch_bounds__(CHUNK)
void eta_sort_kernel(const float* __restrict__ T, const int* __restrict__ eta) {
    __shared__ float logT[N_ETA * N_ETA];
    __shared__ uint16_t ent[SLOTS];
    __shared__ int hist[N_ETA], start[N_ETA + 1], cur[N_ETA];

    const int tid = threadIdx.x;
    const int c = blockIdx.x;
    const int cb = c * CHUNK;
    const int n = min(CHUNK, HW - cb);

    if (tid < N_ETA * N_ETA) logT[tid] = logf(T[tid] + 1e-9f);
    if (tid < N_ETA) hist[tid] = 0;
    for (int s = tid; s < SLOTS; s += CHUNK) ent[s] = 0xFFFFu;
    __syncthreads();

    int myE = 0;
    if (tid < n) {
        int p = cb + tid;
        int r = eta[p] * N_ETA;
        float best = -3.0e38f;
#pragma unroll
        for (int k = 0; k < N_ETA; k++) {
            uint32_t x0 = 0u;
            uint32_t x1 = (uint32_t)(p * 7 + k);
            threefry2x32_k42(x0, x1);
            float v = logT[r + k] + gumbel_from_bits(x0 ^ x1);
            if (v > best) { best = v; myE = k; }
        }
        atomicAdd(&hist[myE], 1);
    }
    __syncthreads();
    if (tid == 0) {
        int s = 0;
        for (int e = 0; e < N_ETA; e++) { start[e] = s; cur[e] = s; s += (hist[e] + 31) & ~31; }
        start[N_ETA] = s;
        g_nsl[c] = s >> 5;
    }
    __syncthreads();
    if (tid < n) {
        int pos = atomicAdd(&cur[myE], 1);
        ent[pos] = (uint16_t)(tid | (myE << 9) | (1 << 12));
    }
    __syncthreads();
    const int nsl32 = start[N_ETA];
    // pad fill: duplicate the group's first (real) pixel, valid=0
    for (int s = tid; s < nsl32; s += CHUNK) {
        if (ent[s] == 0xFFFFu) {
            int e = 0;
#pragma unroll
            for (int k = 1; k < N_ETA; k++) if (s >= start[k]) e = k;
            ent[s] = (uint16_t)((ent[start[e]] & 0x1FF) | (e << 9));
        }
    }
    __syncthreads();
    for (int s = tid; s < nsl32; s += CHUNK) g_sorted[c * SLOTS + s] = ent[s];
}

// ---------------- packed f32x2 + smem/async helpers ----------------
__device__ __forceinline__ unsigned long long pack_ff(float x, float y) {
    unsigned long long r;
    asm("mov.b64 %0, {%1, %2};" : "=l"(r) : "f"(x), "f"(y));
    return r;
}
__device__ __forceinline__ void unpack_ff(float& x, float& y, unsigned long long v) {
    asm("mov.b64 {%0, %1}, %2;" : "=f"(x), "=f"(y) : "l"(v));
}
__device__ __forceinline__ void fma2(unsigned long long& acc, unsigned long long w, unsigned long long v) {
    asm("fma.rn.f32x2 %0, %1, %2, %0;" : "+l"(acc) : "l"(w), "l"(v));
}
__device__ __forceinline__ void lds_v2u64(unsigned long long& a, unsigned long long& b, const float* p) {
    asm("ld.shared.v2.u64 {%0, %1}, [%2];"
        : "=l"(a), "=l"(b) : "l"(__cvta_generic_to_shared(p)));
}
__device__ __forceinline__ unsigned long long lds_u64(const float* p) {
    unsigned long long r;
    asm("ld.shared.u64 %0, [%1];" : "=l"(r) : "l"(__cvta_generic_to_shared(p)));
    return r;
}
__device__ __forceinline__ void cp_async16(float* dst_smem, const float* src_gmem) {
    asm volatile("cp.async.ca.shared.global [%0], [%1], 16;"
                 :: "r"((uint32_t)__cvta_generic_to_shared(dst_smem)), "l"(src_gmem));
}
#define CP_COMMIT()  asm volatile("cp.async.commit_group;" ::: "memory")
#define CP_WAIT(n)   asm volatile("cp.async.wait_group %0;" :: "n"(n) : "memory")

// Per chunk (480 px, one pass): warp = one 32-px same-expert slice.
// feat staged ONCE via double-buffered cp.async; W read via broadcast LDS.128;
// output transposed through smem for coalesced STG.128.
__global__ __launch_bounds__(672, 1)
void compute_kernel(const float* __restrict__ feat, const float* __restrict__ W,
                    const float* __restrict__ b, float* __restrict__ out) {
    extern __shared__ float sh[];
    float* Wt  = sh;                 // [7][68 f][68 o] transposed
    float* bs  = Wt + WSZ;           // 476
    float* buf = bs + 476;           // 2 * TBUF; buf[0] reused as epilogue staging

    const int tid = threadIdx.x;
    const int lane = tid & 31, warp = tid >> 5;

    for (int i = tid; i < WSZ; i += 672) {
        int e = i / (FDIM * FDIM);
        int rem = i - e * (FDIM * FDIM);
        int f = rem / FDIM;
        int o = rem - f * FDIM;
        Wt[i] = W[(e * FDIM + o) * FDIM + f];
    }
    for (int i = tid; i < N_ETA * FDIM; i += 672) bs[i] = b[i];
    __syncthreads();

    for (int c = blockIdx.x; c < NCH; c += gridDim.x) {
        const int cb = c * CHUNK;
        const int n = min(CHUNK, HW - cb);
        const int nf4 = n >> 2;
        const int nsl = g_nsl[c];

        const bool active = (warp < nsl);
        int local = 0, e = 0;
        bool valid = false;
        if (active) {
            uint16_t ent = g_sorted[c * SLOTS + (warp << 5) + lane];
            local = ent & 0x1FF;
            e = (ent >> 9) & 7;
            valid = (ent >> 12) & 1;
        }
        const float* wp = Wt + e * (FDIM * FDIM);
        const float* bp = bs + e * FDIM;

        unsigned long long acc[34];
        if (active) {
#pragma unroll
            for (int q = 0; q < 34; q++) acc[q] = lds_u64(bp + 2 * q);   // broadcast
        }

        // prologue: stage tile 0 (rows 0..7)
        for (int q = tid; q < TROWS * nf4; q += 672) {
            int row = q / nf4, j = q - row * nf4;
            cp_async16(buf + row * CHUNK + 4 * j, feat + (size_t)row * HW + cb + 4 * j);
        }
        CP_COMMIT();

        for (int t = 0; t < 9; t++) {
            const int rows = (t < 8) ? TROWS : 4;     // 68 = 8*8 + 4
            if (t + 1 < 9) {
                const int nrows = (t + 1 < 8) ? TROWS : 4;
                const int f0 = (t + 1) * TROWS;
                float* dst = buf + ((t + 1) & 1) * TBUF;
                for (int q = tid; q < nrows * nf4; q += 672) {
                    int row = q / nf4, j = q - row * nf4;
                    cp_async16(dst + row * CHUNK + 4 * j, feat + (size_t)(f0 + row) * HW + cb + 4 * j);
                }
                CP_COMMIT();
                CP_WAIT(1);
            } else {
                CP_WAIT(0);
            }
            __syncthreads();
            if (active) {
                const float* B = buf + (t & 1) * TBUF + local;
                const float* wrow = wp + t * TROWS * FDIM;
#pragma unroll
                for (int fr = 0; fr < TROWS; fr++) {
                    if (fr < rows) {
                        float v = B[fr * CHUNK];
                        unsigned long long vv = pack_ff(v, v);
#pragma unroll
                        for (int q = 0; q < 17; q++) {
                            unsigned long long lo, hi;
                            lds_v2u64(lo, hi, wrow + 4 * q);   // full-warp broadcast: 1 wf
                            fma2(acc[2 * q], lo, vv);
                            fma2(acc[2 * q + 1], hi, vv);
                        }
                    }
                    wrow += FDIM;
                }
            }
            __syncthreads();
        }

        // epilogue: o-tiles of 8 rows through smem (reuse buf[0]), coalesced STG.128
        float* sm_out = buf;
        for (int ot = 0; ot < 9; ot++) {
            const int rows = (ot < 8) ? 8 : 4;
            if (active && valid) {
#pragma unroll
                for (int qr = 0; qr < 4; qr++) {
                    if (qr * 2 < rows) {
                        float x, y;
                        unpack_ff(x, y, acc[4 * ot + qr]);
                        sm_out[(2 * qr)     * CHUNK + local] = x;
                        sm_out[(2 * qr + 1) * CHUNK + local] = y;
                    }
                }
            }
            __syncthreads();
            const int o0 = ot * 8;
            for (int q = tid; q < rows * nf4; q += 672) {
                int row = q / nf4, j = q - row * nf4;
                float4 v = *(const float4*)(sm_out + row * CHUNK + 4 * j);
                *(float4*)(out + (size_t)(o0 + row) * HW + cb + 4 * j) = v;
            }
            __syncthreads();
        }
    }
}

extern "C" void kernel_launch(void* const* d_in, const int* in_sizes, int n_in,
                              void* d_out, int out_size) {
    const float* x   = 0;   // 35,651,584
    const float* W   = 0;   // 32,368
    const float* b   = 0;   // 476
    const float* T   = 0;   // 49
    const int*   eta = 0;   // 524,288
    for (int i = 0; i < n_in; i++) {
        switch (in_sizes[i]) {
            case 35651584: x   = (const float*)d_in[i]; break;
            case 32368:    W   = (const float*)d_in[i]; break;
            case 476:      b   = (const float*)d_in[i]; break;
            case 49:       T   = (const float*)d_in[i]; break;
            case 524288:   eta = (const int*)d_in[i];   break;
        }
    }
    float* out = (float*)d_out;

    eta_sort_kernel<<<NCH, CHUNK>>>(T, eta);

    int smem = (WSZ + 476 + 2 * TBUF) * (int)sizeof(float);   // 162,096 B
    cudaFuncSetAttribute(compute_kernel, cudaFuncAttributeMaxDynamicSharedMemorySize, smem);
    int dev = 0, sms = 148;
    cudaGetDevice(&dev);
    cudaDeviceGetAttribute(&sms, cudaDevAttrMultiProcessorCount, dev);
    compute_kernel<<<sms, 672, smem>>>(x, W, b, out);
}

// round 9
// speedup vs baseline: 1.3759x; 1.0205x over previous
#include <cuda_runtime.h>
#include <cstdint>

#define N_ETA 7
#define FDIM 68
#define HW (512*1024)
#define CHUNK 512
#define NCH (HW / CHUNK)                 // 1024, exact
#define MAXSL 22                         // worst case: 16 full + 6 pad groups
#define SLOTS (MAXSL*32)                 // 704
#define WSZ (N_ETA*FDIM*FDIM)            // 32368
#define TROWS 17                         // 68 = 4 * 17
#define TBUF (TROWS*CHUNK)               // 8704 floats

__device__ uint16_t g_sorted[NCH * SLOTS];
__device__ int g_nsl[NCH];

// ---------------- threefry2x32, key (0,42), jax partitionable path ----------------
__device__ __forceinline__ void threefry2x32_k42(uint32_t& x0, uint32_t& x1) {
    const uint32_t K2 = 0x1BD11BDAu ^ 0u ^ 42u;
#define TFR(r) { x0 += x1; x1 = __funnelshift_l(x1, x1, (r)); x1 ^= x0; }
    x1 += 42u;
    TFR(13) TFR(15) TFR(26) TFR(6)
    x0 += 42u;  x1 += K2 + 1u;
    TFR(17) TFR(29) TFR(16) TFR(24)
    x0 += K2;   x1 += 0u + 2u;
    TFR(13) TFR(15) TFR(26) TFR(6)
    x1 += 42u + 3u;
    TFR(17) TFR(29) TFR(16) TFR(24)
    x0 += 42u;  x1 += K2 + 4u;
    TFR(13) TFR(15) TFR(26) TFR(6)
    x0 += K2;   x1 += 0u + 5u;
#undef TFR
}

__device__ __forceinline__ float gumbel_from_bits(uint32_t bits) {
    float f = __uint_as_float((bits >> 9) | 0x3F800000u) - 1.0f;
    const float tiny = 1.1754943508222875e-38f;
    float u = fmaxf(tiny, f + tiny);
    return -logf(-logf(u));
}

// eta + chunk-local expert sort into padded 32-px groups.
// entry: bits[0:9)=local px (0..511), [9:12)=expert. Pad slots duplicate the
// group's first real pixel (identical compute + identical store -> benign).
__global__ __launch_bounds__(CHUNK)
void eta_sort_kernel(const float* __restrict__ T, const int* __restrict__ eta) {
    __shared__ float logT[N_ETA * N_ETA];
    __shared__ uint16_t ent[SLOTS];
    __shared__ int hist[N_ETA], start[N_ETA + 1], cur[N_ETA];

    const int tid = threadIdx.x;
    const int c = blockIdx.x;
    const int cb = c * CHUNK;

    if (tid < N_ETA * N_ETA) logT[tid] = logf(T[tid] + 1e-9f);
    if (tid < N_ETA) hist[tid] = 0;
    for (int s = tid; s < SLOTS; s += CHUNK) ent[s] = 0xFFFFu;
    __syncthreads();

    int myE = 0;
    {
        int p = cb + tid;
        int r = eta[p] * N_ETA;
        float best = -3.0e38f;
#pragma unroll
        for (int k = 0; k < N_ETA; k++) {
            uint32_t x0 = 0u;
            uint32_t x1 = (uint32_t)(p * 7 + k);
            threefry2x32_k42(x0, x1);
            float v = logT[r + k] + gumbel_from_bits(x0 ^ x1);
            if (v > best) { best = v; myE = k; }
        }
        atomicAdd(&hist[myE], 1);
    }
    __syncthreads();
    if (tid == 0) {
        int s = 0;
        for (int e = 0; e < N_ETA; e++) { start[e] = s; cur[e] = s; s += (hist[e] + 31) & ~31; }
        start[N_ETA] = s;
        g_nsl[c] = s >> 5;
    }
    __syncthreads();
    {
        int pos = atomicAdd(&cur[myE], 1);
        ent[pos] = (uint16_t)(tid | (myE << 9));
    }
    __syncthreads();
    const int nsl32 = start[N_ETA];
    for (int s = tid; s < nsl32; s += CHUNK) {
        if (ent[s] == 0xFFFFu) {
            int e = 0;
#pragma unroll
            for (int k = 1; k < N_ETA; k++) if (s >= start[k]) e = k;
            ent[s] = ent[start[e]];          // duplicate first real pixel of the group
        }
    }
    __syncthreads();
    for (int s = tid; s < nsl32; s += CHUNK) g_sorted[c * SLOTS + s] = ent[s];
}

// ---------------- packed f32x2 + smem/async helpers ----------------
__device__ __forceinline__ unsigned long long pack_ff(float x, float y) {
    unsigned long long r;
    asm("mov.b64 %0, {%1, %2};" : "=l"(r) : "f"(x), "f"(y));
    return r;
}
__device__ __forceinline__ void unpack_ff(float& x, float& y, unsigned long long v) {
    asm("mov.b64 {%0, %1}, %2;" : "=f"(x), "=f"(y) : "l"(v));
}
__device__ __forceinline__ void fma2(unsigned long long& acc, unsigned long long w, unsigned long long v) {
    asm("fma.rn.f32x2 %0, %1, %2, %0;" : "+l"(acc) : "l"(w), "l"(v));
}
__device__ __forceinline__ void lds_v2u64(unsigned long long& a, unsigned long long& b, const float* p) {
    asm("ld.shared.v2.u64 {%0, %1}, [%2];"
        : "=l"(a), "=l"(b) : "l"(__cvta_generic_to_shared(p)));
}
__device__ __forceinline__ unsigned long long lds_u64(const float* p) {
    unsigned long long r;
    asm("ld.shared.u64 %0, [%1];" : "=l"(r) : "l"(__cvta_generic_to_shared(p)));
    return r;
}
__device__ __forceinline__ void cp_async16(float* dst_smem, const float* src_gmem) {
    asm volatile("cp.async.ca.shared.global [%0], [%1], 16;"
                 :: "r"((uint32_t)__cvta_generic_to_shared(dst_smem)), "l"(src_gmem));
}
#define CP_COMMIT()  asm volatile("cp.async.commit_group;" ::: "memory")
#define CP_WAIT(n)   asm volatile("cp.async.wait_group %0;" :: "n"(n) : "memory")

// Per 512-px chunk, single pass: warp = one 32-px same-expert slice.
// feat staged once (coalesced cp.async, 4 double-buffered 17-row tiles);
// W via full-warp broadcast LDS.128; direct scattered STG epilogue.
__global__ __launch_bounds__(704, 1)
void compute_kernel(const float* __restrict__ feat, const float* __restrict__ W,
                    const float* __restrict__ b, float* __restrict__ out) {
    extern __shared__ float sh[];
    float* Wt  = sh;                 // [7][68 f][68 o] transposed
    float* bs  = Wt + WSZ;           // 476
    float* buf = bs + 476;           // 2 * TBUF

    const int tid = threadIdx.x;
    const int lane = tid & 31, warp = tid >> 5;

    for (int i = tid; i < WSZ; i += 704) {
        int e = i / (FDIM * FDIM);
        int rem = i - e * (FDIM * FDIM);
        int f = rem / FDIM;
        int o = rem - f * FDIM;
        Wt[i] = W[(e * FDIM + o) * FDIM + f];
    }
    for (int i = tid; i < N_ETA * FDIM; i += 704) bs[i] = b[i];
    __syncthreads();

    for (int c = blockIdx.x; c < NCH; c += gridDim.x) {
        const int cb = c * CHUNK;
        const int nsl = g_nsl[c];

        const bool active = (warp < nsl);
        int local = 0, e = 0;
        if (active) {
            uint16_t ent = g_sorted[c * SLOTS + (warp << 5) + lane];
            local = ent & 0x1FF;
            e = ent >> 9;
        }
        const float* wp = Wt + e * (FDIM * FDIM);
        const float* bp = bs + e * FDIM;

        unsigned long long acc[34];
        if (active) {
#pragma unroll
            for (int q = 0; q < 34; q++) acc[q] = lds_u64(bp + 2 * q);   // broadcast
        }

        // prologue: stage tile 0 (rows 0..16), shifts/masks only
        for (int i = tid; i < TROWS * 128; i += 704) {
            int row = i >> 7, col = (i & 127) << 2;
            cp_async16(buf + row * CHUNK + col, feat + (size_t)row * HW + cb + col);
        }
        CP_COMMIT();

        for (int t = 0; t < 4; t++) {
            if (t < 3) {
                const int f0 = (t + 1) * TROWS;
                float* dst = buf + ((t + 1) & 1) * TBUF;
                for (int i = tid; i < TROWS * 128; i += 704) {
                    int row = i >> 7, col = (i & 127) << 2;
                    cp_async16(dst + row * CHUNK + col, feat + (size_t)(f0 + row) * HW + cb + col);
                }
                CP_COMMIT();
                CP_WAIT(1);
            } else {
                CP_WAIT(0);
            }
            __syncthreads();
            if (active) {
                const float* B = buf + (t & 1) * TBUF + local;
                const float* wrow = wp + t * TROWS * FDIM;
#pragma unroll 1
                for (int fr = 0; fr < TROWS; fr++) {
                    float v = B[fr * CHUNK];
                    unsigned long long vv = pack_ff(v, v);
#pragma unroll
                    for (int q = 0; q < 17; q++) {
                        unsigned long long lo, hi;
                        lds_v2u64(lo, hi, wrow + 4 * q);   // full-warp broadcast: 1 wf
                        fma2(acc[2 * q], lo, vv);
                        fma2(acc[2 * q + 1], hi, vv);
                    }
                    wrow += FDIM;
                }
            }
            __syncthreads();
        }

        // epilogue: direct scattered STG within 2KB window (pads store identical
        // data to identical addresses as their group's first lane -> benign)
        if (active) {
            float* op = out + cb + local;
#pragma unroll
            for (int q = 0; q < 34; q++) {
                float x, y;
                unpack_ff(x, y, acc[q]);
                op[(size_t)(2 * q) * HW] = x;
                op[(size_t)(2 * q + 1) * HW] = y;
            }
        }
    }
}

extern "C" void kernel_launch(void* const* d_in, const int* in_sizes, int n_in,
                              void* d_out, int out_size) {
    const float* x   = 0;   // 35,651,584
    const float* W   = 0;   // 32,368
    const float* b   = 0;   // 476
    const float* T   = 0;   // 49
    const int*   eta = 0;   // 524,288
    for (int i = 0; i < n_in; i++) {
        switch (in_sizes[i]) {
            case 35651584: x   = (const float*)d_in[i]; break;
            case 32368:    W   = (const float*)d_in[i]; break;
            case 476:      b   = (const float*)d_in[i]; break;
            case 49:       T   = (const float*)d_in[i]; break;
            case 524288:   eta = (const int*)d_in[i];   break;
        }
    }
    float* out = (float*)d_out;

    eta_sort_kernel<<<NCH, CHUNK>>>(T, eta);

    int smem = (WSZ + 476 + 2 * TBUF) * (int)sizeof(float);   // 201,008 B
    cudaFuncSetAttribute(compute_kernel, cudaFuncAttributeMaxDynamicSharedMemorySize, smem);
    int dev = 0, sms = 148;
    cudaGetDevice(&dev);
    cudaDeviceGetAttribute(&sms, cudaDevAttrMultiProcessorCount, dev);
    compute_kernel<<<sms, 704, smem>>>(x, W, b, out);
}